// round 2
// baseline (speedup 1.0000x reference)
#include <cuda_runtime.h>
#include <cuda_fp16.h>
#include <cstdint>

// ============================================================================
// Efficient_SKAN_Base as ONE fused GEMM: out[b,o] = sum_k A[b,k] * W[k,o] + bias[o]
//   A[b, 0:128]       = silu(x[b,:])
//   A[b, 128j : +128] = sin(grid[j-1] * x[b,:])          j = 1..8
//   W folded: conv_w * coef * scale_sp (and base_weight), fp16, padded layout
// Engine: mma.sync.aligned.m16n8k16 fp16->fp32 (family-generic; tcgen05 is
// rejected by this harness's compute_103 PTX target).
// ============================================================================

#define B_ROWS   131072
#define NUM_F    8
#define NCHUNK   9               // 9 K-blocks of 128 (silu + 8 sin freqs)
#define ROW_H    136             // halves per K-row (128 + 8 pad) -> conflict-free
#define ROW_B    (ROW_H * 2)     // 272 bytes
#define CHUNK_BYTES (128 * ROW_B)   // 34816 per 128x128 fp16 tile
#define XROW_F   132             // x smem row: 128 + 4 pad floats
#define XROW_B   (XROW_F * 4)    // 528 bytes

// Folded fp16 weights [chunk][n][k_padded] + fp32 bias
__device__ __half g_W[NCHUNK * 128 * ROW_H];
__device__ float  g_bias[128];

// ---------------- smem layout ----------------
#define S_X     0
#define S_BIAS  (128 * XROW_B)            // 67584
#define S_A0    (S_BIAS + 512)            // 68096
#define S_A1    (S_A0 + CHUNK_BYTES)
#define S_B0    (S_A1 + CHUNK_BYTES)
#define S_B1    (S_B0 + CHUNK_BYTES)
#define S_TOTAL (S_B1 + CHUNK_BYTES)      // 207360 bytes

// ---------------- helpers ----------------
static __device__ __forceinline__ uint32_t smem_u32(const void* p) {
    uint32_t a;
    asm("{ .reg .u64 t; cvta.to.shared.u64 t, %1; cvt.u32.u64 %0, t; }" : "=r"(a) : "l"(p));
    return a;
}
static __device__ __forceinline__ void cp16(uint32_t s, const void* g) {
    asm volatile("cp.async.cg.shared.global [%0], [%1], 16;" :: "r"(s), "l"(g));
}
static __device__ __forceinline__ void cp_commit() {
    asm volatile("cp.async.commit_group;" ::: "memory");
}
static __device__ __forceinline__ void cp_wait_all() {
    asm volatile("cp.async.wait_group 0;" ::: "memory");
}
static __device__ __forceinline__ uint32_t h2u(__half2 h) {
    return *reinterpret_cast<uint32_t*>(&h);
}

// ============================================================================
// Prep: fold coef & scale_sp into weights, convert fp16, write padded layout.
// g_W flat idx = ((c*128)+n)*ROW_H + kq
// ============================================================================
__global__ void skan_prep(const float* __restrict__ base_w,
                          const float* __restrict__ scale_sp,
                          const float* __restrict__ coef,
                          const float* __restrict__ conv_w,
                          const float* __restrict__ conv_b) {
    int idx = blockIdx.x * 256 + threadIdx.x;
    const int total = NCHUNK * 128 * ROW_H;
    if (idx < total) {
        int c  = idx / (128 * ROW_H);
        int r  = idx % (128 * ROW_H);
        int n  = r / ROW_H;
        int kq = r % ROW_H;
        float v = 0.f;
        if (kq < 128) {
            if (c == 0) {
                v = base_w[n * 128 + kq];
            } else {
                int f = c - 1;
                v = conv_w[f * 16384 + n * 128 + kq] * coef[kq * NUM_F + f] * scale_sp[n];
            }
        }
        g_W[idx] = __float2half_rn(v);
    }
    if (idx < 128) {
        float s = 0.f;
        #pragma unroll
        for (int f = 0; f < NUM_F; f++) s += conv_b[f * 128 + idx];
        g_bias[idx] = s * scale_sp[idx];
    }
}

// ============================================================================
// Feature generation: thread t -> row (t&127), k-half (t>>7). 64 halves/thread,
// written as 8x STS.128 into the padded A buffer (conflict-free, stride 272B).
// ============================================================================
static __device__ __forceinline__ void genA(char* smem, int c, uint32_t a_off,
                                            const float* gf, int tid) {
    const int row = tid & 127;
    const int kh  = tid >> 7;
    const char* xrow = smem + S_X + row * XROW_B + kh * 256;
    char* arow = smem + a_off + row * ROW_B + kh * 128;
    if (c == 0) {
        #pragma unroll
        for (int q = 0; q < 8; q++) {
            float4 x0 = *(const float4*)(xrow + q * 32);
            float4 x1 = *(const float4*)(xrow + q * 32 + 16);
            float v0 = __fdividef(x0.x, 1.f + __expf(-x0.x));
            float v1 = __fdividef(x0.y, 1.f + __expf(-x0.y));
            float v2 = __fdividef(x0.z, 1.f + __expf(-x0.z));
            float v3 = __fdividef(x0.w, 1.f + __expf(-x0.w));
            float v4 = __fdividef(x1.x, 1.f + __expf(-x1.x));
            float v5 = __fdividef(x1.y, 1.f + __expf(-x1.y));
            float v6 = __fdividef(x1.z, 1.f + __expf(-x1.z));
            float v7 = __fdividef(x1.w, 1.f + __expf(-x1.w));
            uint4 pk;
            pk.x = h2u(__floats2half2_rn(v0, v1));
            pk.y = h2u(__floats2half2_rn(v2, v3));
            pk.z = h2u(__floats2half2_rn(v4, v5));
            pk.w = h2u(__floats2half2_rn(v6, v7));
            *(uint4*)(arow + q * 16) = pk;
        }
    } else {
        const float g = gf[c - 1];
        #pragma unroll
        for (int q = 0; q < 8; q++) {
            float4 x0 = *(const float4*)(xrow + q * 32);
            float4 x1 = *(const float4*)(xrow + q * 32 + 16);
            uint4 pk;
            pk.x = h2u(__floats2half2_rn(__sinf(g * x0.x), __sinf(g * x0.y)));
            pk.y = h2u(__floats2half2_rn(__sinf(g * x0.z), __sinf(g * x0.w)));
            pk.z = h2u(__floats2half2_rn(__sinf(g * x1.x), __sinf(g * x1.y)));
            pk.w = h2u(__floats2half2_rn(__sinf(g * x1.z), __sinf(g * x1.w)));
            *(uint4*)(arow + q * 16) = pk;
        }
    }
}

// ============================================================================
// cp.async the pre-folded weight chunk (hot in L2 after first wave)
// ============================================================================
static __device__ __forceinline__ void ldB(uint32_t bbuf, int c, int tid) {
    const char* src = reinterpret_cast<const char*>(g_W) + (size_t)c * CHUNK_BYTES;
    #pragma unroll
    for (int i = tid; i < CHUNK_BYTES / 16; i += 256)
        cp16(bbuf + i * 16, src + i * 16);
}

// ============================================================================
// MMA over one 128-K chunk. Warp grid 4x2: warp_m = wid>>1 (32 rows),
// warp_n = wid&1 (64 cols). Accum 32x64 per warp = float[2][8][4].
// ============================================================================
static __device__ __forceinline__ void mma_chunk(const char* smem, uint32_t a_off,
                                                 uint32_t b_off,
                                                 float acc[2][8][4],
                                                 int wid, int lane) {
    const int wm = wid >> 1, wn = wid & 1;
    const int l4 = lane >> 2, q = lane & 3;
    const char* abase = smem + a_off + (wm * 32 + l4) * ROW_B + q * 4;
    const char* bbase = smem + b_off + (wn * 64 + l4) * ROW_B + q * 4;
    #pragma unroll
    for (int ks = 0; ks < 8; ks++) {
        const int ko = ks * 32;   // 16 halves = 32 bytes per k-step
        uint32_t a[2][4];
        #pragma unroll
        for (int mt = 0; mt < 2; mt++) {
            const char* ap = abase + mt * 16 * ROW_B + ko;
            a[mt][0] = *(const uint32_t*)(ap);
            a[mt][1] = *(const uint32_t*)(ap + 8 * ROW_B);
            a[mt][2] = *(const uint32_t*)(ap + 16);
            a[mt][3] = *(const uint32_t*)(ap + 8 * ROW_B + 16);
        }
        #pragma unroll
        for (int nt = 0; nt < 8; nt++) {
            const char* bp = bbase + nt * 8 * ROW_B + ko;
            uint32_t b0 = *(const uint32_t*)(bp);
            uint32_t b1 = *(const uint32_t*)(bp + 16);
            #pragma unroll
            for (int mt = 0; mt < 2; mt++) {
                asm volatile(
                    "mma.sync.aligned.m16n8k16.row.col.f32.f16.f16.f32 "
                    "{%0,%1,%2,%3},{%4,%5,%6,%7},{%8,%9},{%0,%1,%2,%3};"
                    : "+f"(acc[mt][nt][0]), "+f"(acc[mt][nt][1]),
                      "+f"(acc[mt][nt][2]), "+f"(acc[mt][nt][3])
                    : "r"(a[mt][0]), "r"(a[mt][1]), "r"(a[mt][2]), "r"(a[mt][3]),
                      "r"(b0), "r"(b1));
            }
        }
    }
}

// ============================================================================
__global__ __launch_bounds__(256, 1) void skan_main(const float* __restrict__ x,
                                                    const float* __restrict__ grid,
                                                    float* __restrict__ out) {
    extern __shared__ char smem[];
    const int tid = threadIdx.x;
    const int lane = tid & 31, wid = tid >> 5;
    const size_t m0 = (size_t)blockIdx.x * 128;
    const uint32_t sb = smem_u32(smem);

    float gf[NUM_F];
    #pragma unroll
    for (int f = 0; f < NUM_F; f++) gf[f] = __ldg(grid + f);

    // x tile: gmem-contiguous 64KB -> padded smem rows (coalesced cp.async)
    {
        const char* xg = reinterpret_cast<const char*>(x + m0 * 128);
        #pragma unroll
        for (int k = 0; k < 16; k++) {
            int i = tid + k * 256;
            int row = i >> 5, c16 = i & 31;
            cp16(sb + S_X + row * XROW_B + c16 * 16, xg + (size_t)i * 16);
        }
        cp_commit();
    }
    // prefetch weight chunk 0
    ldB(sb + S_B0, 0, tid);
    cp_commit();

    if (tid < 128) ((float*)(smem + S_BIAS))[tid] = g_bias[tid];

    cp_wait_all();
    __syncthreads();

    // generate feature chunk 0
    genA(smem, 0, S_A0, gf, tid);

    float acc[2][8][4];
    #pragma unroll
    for (int mt = 0; mt < 2; mt++)
        #pragma unroll
        for (int nt = 0; nt < 8; nt++)
            #pragma unroll
            for (int v = 0; v < 4; v++) acc[mt][nt][v] = 0.f;

    // 2-deep pipeline: while MMA(c) runs, cp.async B(c+1) + genA(c+1)
    for (int c = 0; c < NCHUNK; c++) {
        const int buf = c & 1;
        const uint32_t a_off = buf ? S_A1 : S_A0;
        const uint32_t b_off = buf ? S_B1 : S_B0;
        cp_wait_all();       // B(c) landed
        __syncthreads();     // A(c) visible; all warps done reading c-1 bufs
        if (c + 1 < NCHUNK) {
            ldB(sb + (buf ? S_B0 : S_B1), c + 1, tid);
            cp_commit();
        }
        mma_chunk(smem, a_off, b_off, acc, wid, lane);
        if (c + 1 < NCHUNK) genA(smem, c + 1, buf ? S_A0 : S_A1, gf, tid);
    }

    // epilogue: + bias, float2 stores
    {
        const float* bs = (const float*)(smem + S_BIAS);
        const int wm = wid >> 1, wn = wid & 1;
        const int l4 = lane >> 2, q = lane & 3;
        #pragma unroll
        for (int nt = 0; nt < 8; nt++) {
            const int col = wn * 64 + nt * 8 + q * 2;
            const float2 b2 = *(const float2*)(bs + col);
            #pragma unroll
            for (int mt = 0; mt < 2; mt++) {
                const size_t r = m0 + wm * 32 + mt * 16 + l4;
                float2 v0 = make_float2(acc[mt][nt][0] + b2.x, acc[mt][nt][1] + b2.y);
                float2 v1 = make_float2(acc[mt][nt][2] + b2.x, acc[mt][nt][3] + b2.y);
                *(float2*)(out + r * 128 + col)       = v0;
                *(float2*)(out + (r + 8) * 128 + col) = v1;
            }
        }
    }
}

// ============================================================================
extern "C" void kernel_launch(void* const* d_in, const int* in_sizes, int n_in,
                              void* d_out, int out_size) {
    (void)in_sizes; (void)n_in; (void)out_size;
    const float* x        = (const float*)d_in[0];
    const float* grid     = (const float*)d_in[1];
    const float* base_w   = (const float*)d_in[2];
    const float* scale_sp = (const float*)d_in[3];
    const float* coef     = (const float*)d_in[4];
    const float* conv_w   = (const float*)d_in[5];
    const float* conv_b   = (const float*)d_in[6];
    float* out = (float*)d_out;

    cudaFuncSetAttribute(skan_main, cudaFuncAttributeMaxDynamicSharedMemorySize, S_TOTAL);

    const int prep_total = NCHUNK * 128 * ROW_H;
    skan_prep<<<(prep_total + 255) / 256, 256>>>(base_w, scale_sp, coef, conv_w, conv_b);
    skan_main<<<B_ROWS / 128, 256, S_TOTAL>>>(x, grid, out);
}

// round 3
// speedup vs baseline: 1.1863x; 1.1863x over previous
#include <cuda_runtime.h>
#include <cuda_fp16.h>
#include <cstdint>

// ============================================================================
// Efficient_SKAN_Base as ONE fused GEMM: out[b,o] = sum_k A[b,k]*W[k,o] + bias[o]
//   A[b, 0:128]       = silu(x[b,:])
//   A[b, 128j : +128] = sin(grid[j-1] * x[b,:])   j=1..8
// Engine: mma.sync m16n8k16 fp16->fp32, ldmatrix fragment loads,
// x held in registers, feature-gen interleaved into the MMA k-step loop.
// ============================================================================

#define B_ROWS   131072
#define NUM_F    8
#define NCHUNK   9
#define ROW_H    136              // halves per K-row (128 + 8 pad)
#define ROW_B    (ROW_H * 2)      // 272 B (17 x 16B -> conflict-free LDSM/STS)
#define CHUNK_BYTES (128 * ROW_B) // 34816

__device__ __half g_W[NCHUNK * 128 * ROW_H];
__device__ float  g_bias[128];

// smem: A0 A1 B0 B1 double-buffered 128x128 fp16 tiles
#define S_A0 0
#define S_A1 CHUNK_BYTES
#define S_B0 (2 * CHUNK_BYTES)
#define S_B1 (3 * CHUNK_BYTES)
#define S_TOTAL (4 * CHUNK_BYTES)   // 139264 B -> 1 CTA/SM

// ---------------- helpers ----------------
static __device__ __forceinline__ uint32_t smem_u32(const void* p) {
    uint32_t a;
    asm("{ .reg .u64 t; cvta.to.shared.u64 t, %1; cvt.u32.u64 %0, t; }" : "=r"(a) : "l"(p));
    return a;
}
static __device__ __forceinline__ void cp16(uint32_t s, const void* g) {
    asm volatile("cp.async.cg.shared.global [%0], [%1], 16;" :: "r"(s), "l"(g));
}
static __device__ __forceinline__ void cp_commit() {
    asm volatile("cp.async.commit_group;" ::: "memory");
}
static __device__ __forceinline__ void cp_wait_all() {
    asm volatile("cp.async.wait_group 0;" ::: "memory");
}
static __device__ __forceinline__ uint32_t h2u(__half2 h) {
    return *reinterpret_cast<uint32_t*>(&h);
}
static __device__ __forceinline__ void ldsm4(uint32_t* r, uint32_t addr) {
    asm volatile("ldmatrix.sync.aligned.m8n8.x4.shared.b16 {%0,%1,%2,%3}, [%4];"
                 : "=r"(r[0]), "=r"(r[1]), "=r"(r[2]), "=r"(r[3]) : "r"(addr));
}
static __device__ __forceinline__ void hmma(float* d, const uint32_t* a,
                                            uint32_t b0, uint32_t b1) {
    asm volatile("mma.sync.aligned.m16n8k16.row.col.f32.f16.f16.f32 "
                 "{%0,%1,%2,%3},{%4,%5,%6,%7},{%8,%9},{%0,%1,%2,%3};"
                 : "+f"(d[0]), "+f"(d[1]), "+f"(d[2]), "+f"(d[3])
                 : "r"(a[0]), "r"(a[1]), "r"(a[2]), "r"(a[3]), "r"(b0), "r"(b1));
}

// ============================================================================
// Prep: fold coef & scale_sp into weights, fp16, padded layout.
// ============================================================================
__global__ void skan_prep(const float* __restrict__ base_w,
                          const float* __restrict__ scale_sp,
                          const float* __restrict__ coef,
                          const float* __restrict__ conv_w,
                          const float* __restrict__ conv_b) {
    int idx = blockIdx.x * 256 + threadIdx.x;
    const int total = NCHUNK * 128 * ROW_H;
    if (idx < total) {
        int c  = idx / (128 * ROW_H);
        int r  = idx % (128 * ROW_H);
        int n  = r / ROW_H;
        int kq = r % ROW_H;
        float v = 0.f;
        if (kq < 128) {
            if (c == 0) v = base_w[n * 128 + kq];
            else {
                int f = c - 1;
                v = conv_w[f * 16384 + n * 128 + kq] * coef[kq * NUM_F + f] * scale_sp[n];
            }
        }
        g_W[idx] = __float2half_rn(v);
    }
    if (idx < 128) {
        float s = 0.f;
        #pragma unroll
        for (int f = 0; f < NUM_F; f++) s += conv_b[f * 128 + idx];
        g_bias[idx] = s * scale_sp[idx];
    }
}

// cp.async one pre-folded weight chunk into smem
static __device__ __forceinline__ void ldB(uint32_t bbuf, int c, int tid) {
    const char* src = reinterpret_cast<const char*>(g_W) + (size_t)c * CHUNK_BYTES;
    for (int i = tid; i < CHUNK_BYTES / 16; i += 256)
        cp16(bbuf + i * 16, src + (size_t)i * 16);
}

// ============================================================================
__global__ __launch_bounds__(256, 1) void skan_main(const float* __restrict__ x,
                                                    const float* __restrict__ grid,
                                                    float* __restrict__ out) {
    extern __shared__ char smem[];
    const int tid = threadIdx.x;
    const int lane = tid & 31, wid = tid >> 5;
    const size_t m0 = (size_t)blockIdx.x * 128;
    const uint32_t sb = smem_u32(smem);

    // genA ownership: row = tid&127, half kh = tid>>7 (cols kh*64..+64)
    const int grow = tid & 127;
    const int kh = tid >> 7;

    // x in registers: the 64 values this thread converts each chunk
    float4 xv[16];
    {
        const float4* xg = reinterpret_cast<const float4*>(x + (m0 + grow) * 128 + kh * 64);
        #pragma unroll
        for (int j = 0; j < 16; j++) xv[j] = xg[j];
    }

    // prefetch weight chunk 0
    ldB(sb + S_B0, 0, tid);
    cp_commit();

    // generate chunk 0 (silu) into A0
    {
        char* arow = smem + S_A0 + grow * ROW_B + kh * 128;
        #pragma unroll
        for (int ks = 0; ks < 8; ks++) {
            float4 x0 = xv[2 * ks], x1 = xv[2 * ks + 1];
            float v0 = __fdividef(x0.x, 1.f + __expf(-x0.x));
            float v1 = __fdividef(x0.y, 1.f + __expf(-x0.y));
            float v2 = __fdividef(x0.z, 1.f + __expf(-x0.z));
            float v3 = __fdividef(x0.w, 1.f + __expf(-x0.w));
            float v4 = __fdividef(x1.x, 1.f + __expf(-x1.x));
            float v5 = __fdividef(x1.y, 1.f + __expf(-x1.y));
            float v6 = __fdividef(x1.z, 1.f + __expf(-x1.z));
            float v7 = __fdividef(x1.w, 1.f + __expf(-x1.w));
            uint4 pk;
            pk.x = h2u(__floats2half2_rn(v0, v1));
            pk.y = h2u(__floats2half2_rn(v2, v3));
            pk.z = h2u(__floats2half2_rn(v4, v5));
            pk.w = h2u(__floats2half2_rn(v6, v7));
            *(uint4*)(arow + ks * 16) = pk;
        }
    }

    // fragment ldmatrix lane offsets (non-trans for both A and B):
    // A matrices per kstep/mt: {r0-7,kLo},{r8-15,kLo},{r0-7,kHi},{r8-15,kHi}
    const int wm = wid >> 1, wn = wid & 1;
    const uint32_t alo = (uint32_t)(wm * 32 + ((lane >> 3) & 1) * 8 + (lane & 7)) * ROW_B
                       + ((lane >> 4) & 1) * 16;
    // B matrices per LDSM group m: {nt=2m,kLo},{nt=2m,kHi},{nt=2m+1,kLo},{nt=2m+1,kHi}
    const uint32_t blo = (uint32_t)(wn * 64 + ((lane >> 4) & 1) * 8 + (lane & 7)) * ROW_B
                       + ((lane >> 3) & 1) * 16;

    float acc[2][8][4];
    #pragma unroll
    for (int mt = 0; mt < 2; mt++)
        #pragma unroll
        for (int nt = 0; nt < 8; nt++)
            #pragma unroll
            for (int v = 0; v < 4; v++) acc[mt][nt][v] = 0.f;

    #pragma unroll 1
    for (int c = 0; c < NCHUNK; c++) {
        cp_wait_all();        // weight chunk c landed
        __syncthreads();      // A(c) visible; prev-chunk buffers free

        const int buf = c & 1;
        const uint32_t abuf = sb + (buf ? S_A1 : S_A0);
        const uint32_t bbuf = sb + (buf ? S_B1 : S_B0);
        char* anext = smem + (buf ? S_A0 : S_A1) + grow * ROW_B + kh * 128;

        const bool gen = (c + 1 < NCHUNK);
        float g = 0.f;
        if (gen) {
            g = __ldg(grid + c);                   // chunk c+1 frequency
            ldB(sb + (buf ? S_B0 : S_B1), c + 1, tid);
            cp_commit();
        }

        #pragma unroll
        for (int ks = 0; ks < 8; ks++) {
            uint32_t a0r[4], a1r[4];
            ldsm4(a0r, abuf + alo + ks * 32);
            ldsm4(a1r, abuf + alo + 16 * ROW_B + ks * 32);
            #pragma unroll
            for (int m = 0; m < 4; m++) {
                uint32_t br[4];
                ldsm4(br, bbuf + blo + (uint32_t)m * 16 * ROW_B + ks * 32);
                hmma(acc[0][2 * m],     a0r, br[0], br[1]);
                hmma(acc[0][2 * m + 1], a0r, br[2], br[3]);
                hmma(acc[1][2 * m],     a1r, br[0], br[1]);
                hmma(acc[1][2 * m + 1], a1r, br[2], br[3]);
            }
            if (gen) {   // one slice of sin-feature gen for chunk c+1
                float4 x0 = xv[2 * ks], x1 = xv[2 * ks + 1];
                uint4 pk;
                pk.x = h2u(__floats2half2_rn(__sinf(g * x0.x), __sinf(g * x0.y)));
                pk.y = h2u(__floats2half2_rn(__sinf(g * x0.z), __sinf(g * x0.w)));
                pk.z = h2u(__floats2half2_rn(__sinf(g * x1.x), __sinf(g * x1.y)));
                pk.w = h2u(__floats2half2_rn(__sinf(g * x1.z), __sinf(g * x1.w)));
                *(uint4*)(anext + ks * 16) = pk;
            }
        }
    }

    // epilogue: + bias, float2 stores (bias via __ldg, L2-hot)
    {
        const int l4 = lane >> 2, q = lane & 3;
        #pragma unroll
        for (int nt = 0; nt < 8; nt++) {
            const int col = wn * 64 + nt * 8 + q * 2;
            const float bx = __ldg(g_bias + col);
            const float by = __ldg(g_bias + col + 1);
            #pragma unroll
            for (int mt = 0; mt < 2; mt++) {
                const size_t r = m0 + wm * 32 + mt * 16 + l4;
                float2 v0 = make_float2(acc[mt][nt][0] + bx, acc[mt][nt][1] + by);
                float2 v1 = make_float2(acc[mt][nt][2] + bx, acc[mt][nt][3] + by);
                *(float2*)(out + r * 128 + col)       = v0;
                *(float2*)(out + (r + 8) * 128 + col) = v1;
            }
        }
    }
}

// ============================================================================
extern "C" void kernel_launch(void* const* d_in, const int* in_sizes, int n_in,
                              void* d_out, int out_size) {
    (void)in_sizes; (void)n_in; (void)out_size;
    const float* x        = (const float*)d_in[0];
    const float* grid     = (const float*)d_in[1];
    const float* base_w   = (const float*)d_in[2];
    const float* scale_sp = (const float*)d_in[3];
    const float* coef     = (const float*)d_in[4];
    const float* conv_w   = (const float*)d_in[5];
    const float* conv_b   = (const float*)d_in[6];
    float* out = (float*)d_out;

    cudaFuncSetAttribute(skan_main, cudaFuncAttributeMaxDynamicSharedMemorySize, S_TOTAL);

    const int prep_total = NCHUNK * 128 * ROW_H;
    skan_prep<<<(prep_total + 255) / 256, 256>>>(base_w, scale_sp, coef, conv_w, conv_b);
    skan_main<<<B_ROWS / 128, 256, S_TOTAL>>>(x, grid, out);
}